// round 14
// baseline (speedup 1.0000x reference)
#include <cuda_runtime.h>
#include <cuda_bf16.h>
#include <cstdint>

// Shapes: batch_x [32,4096,128] -> N=4096 rows x 4096 (I=64 patches, L=64)
//         pred    [32,1024,128] -> N=4096 rows x 1024 (J=16 patches, L=64)
//
// Math (sum_l q_jl = 1 => lse_i cancels in softmax over j):
//   dot_ij = q_j . x_i (raw x);  u_ij = ne_j - dot_ij  (ne_j = sum q log q)
//   loss = mean_n [ sum_i ( sum_j softmax_j(u_ij)*u_ij + lse_i ) ]
//
// Tensor-core (m16n8k8 tf32) + multi-row software pipeline: each CTA handles
// ITERS rows; x and raw pred for row it+1 stream in via double-buffered
// cp.async while row it computes. lse reads exact f32 smem.
#define NROWS 4096
#define SEQ   4096
#define PREDL 1024
#define ITERS 4
#define NCTAS (NROWS / ITERS)   // 1024
#define XSTR  68
#define QSTR  68

__device__ float g_blk_sum[NCTAS];
__device__ unsigned g_ctr = 0;

__device__ __forceinline__ void mma_tf32(float d[4],
                                         uint32_t a0, uint32_t a1,
                                         uint32_t a2, uint32_t a3,
                                         uint32_t b0, uint32_t b1) {
    asm volatile(
        "mma.sync.aligned.m16n8k8.row.col.f32.tf32.tf32.f32 "
        "{%0,%1,%2,%3}, {%4,%5,%6,%7}, {%8,%9}, {%0,%1,%2,%3};"
        : "+f"(d[0]), "+f"(d[1]), "+f"(d[2]), "+f"(d[3])
        : "r"(a0), "r"(a1), "r"(a2), "r"(a3), "r"(b0), "r"(b1));
}

__device__ __forceinline__ void cp_async16(uint32_t smem_addr, const void* gptr) {
    asm volatile("cp.async.ca.shared.global [%0], [%1], 16;"
                 :: "r"(smem_addr), "l"(gptr));
}

__global__ __launch_bounds__(128, 4)
void kl_fused_kernel(const float* __restrict__ x, const float* __restrict__ pred,
                     float* __restrict__ out) {
    __shared__ __align__(16) float xs[2][64 * XSTR];    // 34.8KB (double buf)
    __shared__ __align__(16) float praw[2][PREDL];      // 8KB (double buf)
    __shared__ __align__(16) float qs[16 * QSTR];       // 4.35KB
    __shared__ __align__(16) float ne_s[16];
    __shared__ float red[4];
    __shared__ int   is_last_sh;

    const int t    = threadIdx.x;
    const int warp = t >> 5;
    const int lane = t & 31;
    const int n0   = blockIdx.x * ITERS;

    const int gid  = lane >> 2;
    const int tid4 = lane & 3;
    const int mb   = 16 * warp;              // warp's m-tile base

    float loss_acc = 0.f;

    // ---- prefetch row 0 (x + raw pred) ----
    {
        const float4* x4 = (const float4*)(x + (size_t)n0 * SEQ);
        #pragma unroll
        for (int k = 0; k < 8; k++) {
            const int idx = t + 128 * k;     // 1024 float4s
            uint32_t dst = (uint32_t)__cvta_generic_to_shared(
                (float4*)(xs[0] + (idx >> 4) * XSTR) + (idx & 15));
            cp_async16(dst, x4 + idx);
        }
        const float4* p4 = (const float4*)(pred + (size_t)n0 * PREDL);
        #pragma unroll
        for (int k = 0; k < 2; k++) {
            const int idx = t + 128 * k;     // 256 float4s
            uint32_t dst = (uint32_t)__cvta_generic_to_shared(
                (float4*)praw[0] + idx);
            cp_async16(dst, p4 + idx);
        }
        asm volatile("cp.async.commit_group;" ::: "memory");
    }

    #pragma unroll
    for (int it = 0; it < ITERS; it++) {
        const int buf = it & 1;

        // ---- prefetch row it+1 into the other buffer ----
        if (it + 1 < ITERS) {
            const int nb = n0 + it + 1;
            const int b2 = (it + 1) & 1;
            const float4* x4 = (const float4*)(x + (size_t)nb * SEQ);
            #pragma unroll
            for (int k = 0; k < 8; k++) {
                const int idx = t + 128 * k;
                uint32_t dst = (uint32_t)__cvta_generic_to_shared(
                    (float4*)(xs[b2] + (idx >> 4) * XSTR) + (idx & 15));
                cp_async16(dst, x4 + idx);
            }
            const float4* p4 = (const float4*)(pred + (size_t)nb * PREDL);
            #pragma unroll
            for (int k = 0; k < 2; k++) {
                const int idx = t + 128 * k;
                uint32_t dst = (uint32_t)__cvta_generic_to_shared(
                    (float4*)praw[b2] + idx);
                cp_async16(dst, p4 + idx);
            }
            asm volatile("cp.async.commit_group;" ::: "memory");
            asm volatile("cp.async.wait_group 1;" ::: "memory");
        } else {
            asm volatile("cp.async.wait_group 0;" ::: "memory");
        }
        __syncthreads();   // row it buffers ready

        // ---- Phase B: praw[buf] -> q smem [j][68] + ne_j ----
        {
            const float4* pr4 = (const float4*)praw[buf];
            #pragma unroll
            for (int k = 0; k < 2; k++) {
                const int idx = t + 128 * k;
                float4 v = pr4[idx];
                const int j = idx >> 4;
                // naive expsum (inputs ~N(0,1), fp32-safe; validated)
                float e0 = __expf(v.x), e1 = __expf(v.y);
                float e2 = __expf(v.z), e3 = __expf(v.w);
                float E = e0 + e1 + e2 + e3;
                float S = e0 * v.x + e1 * v.y + e2 * v.z + e3 * v.w;
                #pragma unroll
                for (int o = 8; o; o >>= 1) {
                    E += __shfl_xor_sync(0xffffffffu, E, o);
                    S += __shfl_xor_sync(0xffffffffu, S, o);
                }
                float rinv = __frcp_rn(E);
                ((float4*)(qs + j * QSTR))[idx & 15] =
                    make_float4(e0 * rinv, e1 * rinv, e2 * rinv, e3 * rinv);
                if ((lane & 15) == 0) ne_s[j] = S * rinv - __logf(E);
            }
        }
        __syncthreads();   // qs/ne ready for all warps

        // ---- Phase C: tensor-core GEMM (warp covers patches mb..mb+15) ----
        const uint32_t* xu = (const uint32_t*)xs[buf];
        const uint32_t* qu = (const uint32_t*)qs;

        float d[2][4];
        #pragma unroll
        for (int nt = 0; nt < 2; nt++)
            #pragma unroll
            for (int rg = 0; rg < 4; rg++) d[nt][rg] = 0.f;

        #pragma unroll
        for (int kt = 0; kt < 8; kt++) {
            const int c = 8 * kt + tid4;
            uint32_t b00 = qu[gid * QSTR + c];
            uint32_t b01 = qu[gid * QSTR + c + 4];
            uint32_t b10 = qu[(8 + gid) * QSTR + c];
            uint32_t b11 = qu[(8 + gid) * QSTR + c + 4];
            const int rowb = (mb + gid) * XSTR;
            uint32_t a0 = xu[rowb + c];
            uint32_t a1 = xu[rowb + 8 * XSTR + c];
            uint32_t a2 = xu[rowb + c + 4];
            uint32_t a3 = xu[rowb + 8 * XSTR + c + 4];
            mma_tf32(d[0], a0, a1, a2, a3, b00, b01);
            mma_tf32(d[1], a0, a1, a2, a3, b10, b11);
        }

        // ---- softmax over j per patch row ----
        const float ne0 = ne_s[2 * tid4];
        const float ne1 = ne_s[2 * tid4 + 1];
        const float ne2 = ne_s[8 + 2 * tid4];
        const float ne3 = ne_s[8 + 2 * tid4 + 1];
        float csum = 0.f;
        #pragma unroll
        for (int half = 0; half < 2; half++) {
            float u0 = ne0 - d[0][2 * half + 0];
            float u1 = ne1 - d[0][2 * half + 1];
            float u2 = ne2 - d[1][2 * half + 0];
            float u3 = ne3 - d[1][2 * half + 1];
            float mx = fmaxf(fmaxf(u0, u1), fmaxf(u2, u3));
            mx = fmaxf(mx, __shfl_xor_sync(0xffffffffu, mx, 1));
            mx = fmaxf(mx, __shfl_xor_sync(0xffffffffu, mx, 2));
            float e0 = __expf(u0 - mx), e1 = __expf(u1 - mx);
            float e2 = __expf(u2 - mx), e3 = __expf(u3 - mx);
            float E  = e0 + e1 + e2 + e3;
            float EU = e0 * u0 + e1 * u1 + e2 * u2 + e3 * u3;
            E  += __shfl_xor_sync(0xffffffffu, E, 1);
            EU += __shfl_xor_sync(0xffffffffu, EU, 1);
            E  += __shfl_xor_sync(0xffffffffu, E, 2);
            EU += __shfl_xor_sync(0xffffffffu, EU, 2);
            if (tid4 == 0) csum += __fdividef(EU, E);
        }

        // ---- lse: 2 lanes per patch (p = t>>1, half = t&1), exact f32 ----
        float Ep = 0.f;
        {
            const int p = t >> 1;
            const int hc = 8 * (t & 1);
            const float4* xp4 = (const float4*)(xs[buf] + p * XSTR) + hc;
            #pragma unroll
            for (int c = 0; c < 8; c++) {
                float4 v = xp4[c];
                Ep += __expf(v.x) + __expf(v.y) + __expf(v.z) + __expf(v.w);
            }
        }
        Ep += __shfl_xor_sync(0xffffffffu, Ep, 1);
        float my = csum;
        if ((t & 1) == 0) my += __logf(Ep);
        loss_acc += my;

        __syncthreads();   // protect xs[buf]/praw[buf]/qs before next overwrite
    }

    // ---- reductions: warp -> CTA -> grid (deterministic) ----
    float my = loss_acc;
    #pragma unroll
    for (int o = 16; o; o >>= 1) my += __shfl_xor_sync(0xffffffffu, my, o);
    if (lane == 0) red[warp] = my;
    __syncthreads();
    if (t == 0) {
        g_blk_sum[blockIdx.x] = (red[0] + red[1]) + (red[2] + red[3]);
        __threadfence();
        unsigned prev = atomicAdd(&g_ctr, 1u);
        is_last_sh = (prev == NCTAS - 1);
    }
    __syncthreads();

    if (is_last_sh) {
        float s = 0.f;
        #pragma unroll 4
        for (int i = t; i < NCTAS; i += 128) s += g_blk_sum[i];
        #pragma unroll
        for (int o = 16; o; o >>= 1) s += __shfl_xor_sync(0xffffffffu, s, o);
        if (lane == 0) red[warp] = s;
        __syncthreads();
        if (t == 0) {
            out[0] = ((red[0] + red[1]) + (red[2] + red[3])) * (1.0f / (float)NROWS);
            g_ctr = 0;
        }
    }
}

extern "C" void kernel_launch(void* const* d_in, const int* in_sizes, int n_in,
                              void* d_out, int out_size) {
    const float* x = nullptr;
    const float* pred = nullptr;
    for (int i = 0; i < n_in; i++) {
        if (in_sizes[i] == 32 * 4096 * 128)      x    = (const float*)d_in[i];
        else if (in_sizes[i] == 32 * 1024 * 128) pred = (const float*)d_in[i];
    }
    kl_fused_kernel<<<NCTAS, 128>>>(x, pred, (float*)d_out);
}